// round 15
// baseline (speedup 1.0000x reference)
#include <cuda_runtime.h>
#include <cuda_fp16.h>
#include <cstdint>

#define CDIV(a,b) (((a)+(b)-1)/(b))

static constexpr int T_TOK = 8192;
static constexpr int DM    = 1024;
static constexpr int DFF   = 4096;
static constexpr int NE    = 8;
static constexpr int TOPK  = 2;
static constexpr int SLOTS = T_TOK * TOPK;      // 16384 routed slots

static constexpr int TM      = 128;
static constexpr int TN      = 128;
static constexpr int KC      = 32;              // K halfs per stage (64B row)
static constexpr int STAGES  = 3;
static constexpr int PADB    = 80;              // bytes per smem row (64 + 16 pad)
static constexpr int THREADS = 256;             // 8 warps, warp tile 32x64
static constexpr int MAXT    = SLOTS/TM + NE;   // 136 worst-case M tiles

static constexpr int A_STAGE_B   = TM * PADB;            // 10240
static constexpr int STAGE_BYTES = (TM + TN) * PADB;     // 20480
static constexpr int SMEM_TOTAL  = STAGES * STAGE_BYTES; // 61440 (3 CTA/SM = 184 KB)

// ---- device scratch (__device__ globals = sanctioned scratch path) ----
__device__ int      g_cnt[NE];                  // zeroed by k_sched tail (replay-safe)
__device__ int      g_cntc[NE];
__device__ int      g_base[NE];
__device__ int      g_toff[NE + 1];
__device__ int      g_tok[NE][SLOTS];
__device__ uint32_t g_sp[SLOTS];                // per input slot: (e<<28)|pos
__device__ __half   g_h  [(size_t)SLOTS * DFF]; // 134 MB fp16 activations
__device__ float    g_y  [(size_t)SLOTS * DM];  // 67 MB fp32 per-slot GEMM2 output
__device__ __half   g_xh [(size_t)T_TOK * DM];
__device__ __half   g_wih[(size_t)NE * DFF * DM];
__device__ __half   g_woh[(size_t)NE * DM * DFF];

// ---------------------------------------------------------------- helpers
__device__ __forceinline__ uint32_t smem_u32(const void* p) {
    uint32_t a;
    asm("{ .reg .u64 t; cvta.to.shared.u64 t, %1; cvt.u32.u64 %0, t; }" : "=r"(a) : "l"(p));
    return a;
}

__device__ __forceinline__ void ldsm_x4(uint32_t r[4], uint32_t addr) {
    asm volatile("ldmatrix.sync.aligned.m8n8.x4.shared.b16 {%0,%1,%2,%3}, [%4];"
        : "=r"(r[0]), "=r"(r[1]), "=r"(r[2]), "=r"(r[3]) : "r"(addr));
}

__device__ __forceinline__ void mma_fp16(float c[4], const uint32_t a[4], uint32_t b0, uint32_t b1) {
    asm volatile(
        "mma.sync.aligned.m16n8k16.row.col.f32.f16.f16.f32 "
        "{%0,%1,%2,%3}, {%4,%5,%6,%7}, {%8,%9}, {%0,%1,%2,%3};"
        : "+f"(c[0]), "+f"(c[1]), "+f"(c[2]), "+f"(c[3])
        : "r"(a[0]), "r"(a[1]), "r"(a[2]), "r"(a[3]), "r"(b0), "r"(b1));
}

__device__ __forceinline__ void cpa16(uint32_t dst, const void* src, bool p) {
    int sz = p ? 16 : 0;
    asm volatile("cp.async.cg.shared.global [%0], [%1], 16, %2;\n" :: "r"(dst), "l"(src), "r"(sz));
}

// ---------------------------------------------------------------- small kernels
// one launch converts x, wi, wo -> fp16
__global__ void k_conv3(const float4* __restrict__ x,  __half2* __restrict__ xh,  int nx,
                        const float4* __restrict__ wi, __half2* __restrict__ wih,
                        const float4* __restrict__ wo, __half2* __restrict__ woh, int nw)
{
    int i = blockIdx.x * blockDim.x + threadIdx.x;
    const float4* src; __half2* dst; int j;
    if (i < nx)              { src = x;  dst = xh;  j = i; }
    else if (i < nx + nw)    { src = wi; dst = wih; j = i - nx; }
    else if (i < nx + 2*nw)  { src = wo; dst = woh; j = i - nx - nw; }
    else return;
    float4 v = src[j];
    dst[2 * j]     = __floats2half2_rn(v.x, v.y);
    dst[2 * j + 1] = __floats2half2_rn(v.z, v.w);
}

__global__ void k_route(const int* __restrict__ sel, const float* __restrict__ rw) {
    int s = blockIdx.x * blockDim.x + threadIdx.x;
    if (s >= SLOTS) return;
    const int* v = sel + (size_t)s * NE;
    int e = 0;
    #pragma unroll
    for (int i = 1; i < NE; i++) if (v[i] != 0) e = i;
    int pos = atomicAdd(&g_cnt[e], 1);
    g_tok[e][pos] = s / TOPK;
    g_sp[s] = ((uint32_t)e << 28) | (uint32_t)pos;
}

__global__ void k_sched() {
    int b = 0, t = 0;
    for (int e = 0; e < NE; e++) {
        g_base[e] = b; g_toff[e] = t;
        int c = g_cnt[e];
        g_cntc[e] = c;
        g_cnt[e] = 0;                 // self-clean for next graph replay
        b += c;
        t += (c + TM - 1) / TM;
    }
    g_toff[NE] = t;
}

__global__ void k_combine(const float* __restrict__ rw, float4* __restrict__ out) {
    int idx = blockIdx.x * blockDim.x + threadIdx.x;     // T * 256
    int t = idx >> 8, j = idx & 255;
    uint32_t sp0 = g_sp[2 * t], sp1 = g_sp[2 * t + 1];
    size_t s0 = (size_t)(g_base[sp0 >> 28] + (int)(sp0 & 0x0FFFFFFF));
    size_t s1 = (size_t)(g_base[sp1 >> 28] + (int)(sp1 & 0x0FFFFFFF));
    float w0 = rw[2 * t], w1 = rw[2 * t + 1];
    const float4* y = (const float4*)g_y;
    float4 a = y[s0 * 256 + j];
    float4 b = y[s1 * 256 + j];
    float4 o;
    o.x = w0 * a.x + w1 * b.x;
    o.y = w0 * a.y + w1 * b.y;
    o.z = w0 * a.z + w1 * b.z;
    o.w = w0 * a.w + w1 * b.w;
    out[idx] = o;
}

// ---------------------------------------------------------------- grouped fp16 GEMM
// FIRST:  h[slot,n] = fp16(relu( x[tok,:] . wi[e][n,:] ))   KD=DM,  Ntot=DFF
// !FIRST: y[slot,n] = h[slot,:] . wo[e][n,:]                KD=DFF, Ntot=DM
template <bool FIRST, int KD>
__global__ __launch_bounds__(THREADS, 3) void k_gemm(const __half* __restrict__ Xin,
                                                     const __half* __restrict__ Wm)
{
    extern __shared__ char smem[];
    constexpr int Ntot = FIRST ? DFF : DM;
    constexpr int NK   = KD / KC;
    constexpr int KI   = KC / 16;                  // 2 kk-groups per stage

    int bx = blockIdx.x;
    int total = g_toff[NE];
    if (bx >= total) return;

    int e = 0;
    #pragma unroll
    for (int i = 1; i < NE; i++) if (bx >= g_toff[i]) e = i;
    int m0 = (bx - g_toff[e]) * TM, cnt = g_cntc[e], base = g_base[e];
    int n0 = blockIdx.y * TN;

    int tid  = threadIdx.x;
    int lane = tid & 31, w = tid >> 5;
    int g = lane >> 2, t4 = lane & 3;

    uint32_t sb = smem_u32(smem);

    // ---- loaders. A: 2 thr/row x 32B (rows 0-127). B: 2 thr/row x 32B (rows 0-127).
    int rr = tid >> 1;
    int co = (tid & 1) * 32;                        // byte offset in 64B row
    int mrowA = m0 + rr;
    bool aok = mrowA < cnt;
    const __half* aSrc;
    if (FIRST) {
        int tok = aok ? g_tok[e][mrowA] : 0;
        aSrc = Xin + (size_t)tok * KD;
    } else {
        aSrc = g_h + (size_t)(base + (aok ? mrowA : 0)) * KD;
    }
    const __half* bSrc = Wm + ((size_t)e * Ntot + n0 + rr) * KD;

    uint32_t aDst = sb + rr * PADB + co;
    uint32_t bDst = sb + A_STAGE_B + rr * PADB + co;

    auto load_stage = [&](int s) {
        uint32_t st = (uint32_t)((s % STAGES) * STAGE_BYTES);
        const __half* ap = aSrc + s * KC + co / 2;
        const __half* bp = bSrc + s * KC + co / 2;
        cpa16(aDst + st,      ap,     aok);
        cpa16(aDst + st + 16, ap + 8, aok);
        cpa16(bDst + st,      bp,     true);
        cpa16(bDst + st + 16, bp + 8, true);
    };

    #pragma unroll
    for (int s = 0; s < STAGES - 1; s++) {
        load_stage(s);
        asm volatile("cp.async.commit_group;\n");
    }

    // ---- warp tile 32x64: warps (4 m) x (2 n)
    int wm0 = (w & 3) * 32, wn0 = (w >> 2) * 64;
    int lrow = lane & 15;
    int khiB = ((lane >> 4) << 4);                  // 0 or 16B: k-half select

    uint32_t aOff[2], bOff[4];
    #pragma unroll
    for (int ms = 0; ms < 2; ms++)
        aOff[ms] = sb + (uint32_t)((wm0 + ms * 16 + lrow) * PADB) + khiB;
    #pragma unroll
    for (int nb = 0; nb < 4; nb++)
        bOff[nb] = sb + (uint32_t)(A_STAGE_B + (wn0 + nb * 16 + lrow) * PADB) + khiB;

    float acc[2][8][4];
    #pragma unroll
    for (int i = 0; i < 2; i++)
        #pragma unroll
        for (int j = 0; j < 8; j++)
            #pragma unroll
            for (int q = 0; q < 4; q++) acc[i][j][q] = 0.f;

    for (int s = 0; s < NK; s++) {
        asm volatile("cp.async.wait_group %0;\n" :: "n"(STAGES - 2));
        __syncthreads();

        // issue next gmem->smem loads (buffer (s+2)%3 — readers done before sync above)
        if (s + STAGES - 1 < NK) load_stage(s + STAGES - 1);
        asm volatile("cp.async.commit_group;\n");

        uint32_t st = (uint32_t)((s % STAGES) * STAGE_BYTES);
        #pragma unroll
        for (int kki = 0; kki < KI; kki++) {
            uint32_t kb = (uint32_t)(kki * 32);     // 16 halfs = 32B
            uint32_t a[2][4];
            #pragma unroll
            for (int ms = 0; ms < 2; ms++) ldsm_x4(a[ms], aOff[ms] + st + kb);
            #pragma unroll
            for (int nb = 0; nb < 4; nb++) {
                uint32_t bq[4];
                ldsm_x4(bq, bOff[nb] + st + kb);
                #pragma unroll
                for (int ms = 0; ms < 2; ms++) {
                    mma_fp16(acc[ms][nb * 2],     a[ms], bq[0], bq[2]);
                    mma_fp16(acc[ms][nb * 2 + 1], a[ms], bq[1], bq[3]);
                }
            }
        }
    }

    // ---- epilogue (no atomics: per-slot scratch)
    #pragma unroll
    for (int ms = 0; ms < 2; ms++) {
        #pragma unroll
        for (int half = 0; half < 2; half++) {
            int lr   = wm0 + ms * 16 + half * 8 + g;
            int mrow = m0 + lr;
            if (mrow < cnt) {
                if (FIRST) {
                    __half* hp = g_h + (size_t)(base + mrow) * DFF + n0 + wn0;
                    #pragma unroll
                    for (int ns = 0; ns < 8; ns++) {
                        float v0 = fmaxf(acc[ms][ns][half * 2 + 0], 0.f);
                        float v1 = fmaxf(acc[ms][ns][half * 2 + 1], 0.f);
                        *reinterpret_cast<__half2*>(hp + ns * 8 + 2 * t4) = __floats2half2_rn(v0, v1);
                    }
                } else {
                    float* yp = g_y + (size_t)(base + mrow) * DM + n0 + wn0;
                    #pragma unroll
                    for (int ns = 0; ns < 8; ns++) {
                        float2 st2;
                        st2.x = acc[ms][ns][half * 2 + 0];
                        st2.y = acc[ms][ns][half * 2 + 1];
                        *reinterpret_cast<float2*>(yp + ns * 8 + 2 * t4) = st2;
                    }
                }
            }
        }
    }
}

// ---------------------------------------------------------------- launch
extern "C" void kernel_launch(void* const* d_in, const int* in_sizes, int n_in,
                              void* d_out, int out_size)
{
    const float* x   = (const float*)d_in[0];   // [T, DM]
    const int*   sel = (const int*)  d_in[1];   // [T, K, E] one-hot int32
    const float* rw  = (const float*)d_in[2];   // [T, K]
    const float* wi  = (const float*)d_in[3];   // [E, DFF, DM]
    const float* wo  = (const float*)d_in[4];   // [E, DM, DFF]
    float* out = (float*)d_out;                 // [T, DM]

    __half* xh;  cudaGetSymbolAddress((void**)&xh,  g_xh);
    __half* wih; cudaGetSymbolAddress((void**)&wih, g_wih);
    __half* woh; cudaGetSymbolAddress((void**)&woh, g_woh);

    cudaFuncSetAttribute(k_gemm<true,  DM >, cudaFuncAttributeMaxDynamicSharedMemorySize, SMEM_TOTAL);
    cudaFuncSetAttribute(k_gemm<false, DFF>, cudaFuncAttributeMaxDynamicSharedMemorySize, SMEM_TOTAL);

    int nx = T_TOK * DM / 4;
    int nw = NE * DFF * DM / 4;

    k_conv3<<<CDIV(nx + 2 * nw, 256), 256>>>((const float4*)x,  (__half2*)xh,  nx,
                                             (const float4*)wi, (__half2*)wih,
                                             (const float4*)wo, (__half2*)woh, nw);   // 1
    k_route<<<CDIV(SLOTS, 256), 256>>>(sel, rw);                                      // 2
    k_sched<<<1, 1>>>();                                                              // 3
    k_gemm<true,  DM ><<<dim3(MAXT, DFF / TN), THREADS, SMEM_TOTAL>>>(xh, wih);       // 4 (profiled)
    k_gemm<false, DFF><<<dim3(MAXT, DM  / TN), THREADS, SMEM_TOTAL>>>(nullptr, woh);  // 5
    k_combine<<<CDIV(T_TOK * DM / 4, 256), 256>>>(rw, (float4*)out);                  // 6
}

// round 16
// speedup vs baseline: 1.5836x; 1.5836x over previous
#include <cuda_runtime.h>
#include <cuda_fp16.h>
#include <cstdint>

#define CDIV(a,b) (((a)+(b)-1)/(b))

static constexpr int T_TOK = 8192;
static constexpr int DM    = 1024;
static constexpr int DFF   = 4096;
static constexpr int NE    = 8;
static constexpr int TOPK  = 2;
static constexpr int SLOTS = T_TOK * TOPK;      // 16384 routed slots

static constexpr int TM      = 128;
static constexpr int TN      = 64;
static constexpr int KC      = 32;              // K halfs per stage (64B row)
static constexpr int STAGES  = 4;
static constexpr int PADB    = 80;              // bytes per smem row (64 + 16 pad)
static constexpr int THREADS = 256;             // 8 warps, warp tile 32x32
static constexpr int MAXT    = SLOTS/TM + NE;   // 136 worst-case M tiles

static constexpr int A_STAGE_B   = TM * PADB;            // 10240
static constexpr int STAGE_BYTES = (TM + TN) * PADB;     // 15360
static constexpr int SMEM_TOTAL  = STAGES * STAGE_BYTES; // 61440 (3 CTA/SM = 184 KB)

// ---- device scratch (__device__ globals = sanctioned scratch path) ----
__device__ int      g_cnt[NE];                  // zeroed by k_sched tail (replay-safe)
__device__ int      g_cntc[NE];
__device__ int      g_base[NE];
__device__ int      g_toff[NE + 1];
__device__ int      g_tok[NE][SLOTS];
__device__ uint32_t g_sp[SLOTS];                // per input slot: (e<<28)|pos
__device__ __half   g_h  [(size_t)SLOTS * DFF]; // 134 MB fp16 activations
__device__ float    g_y  [(size_t)SLOTS * DM];  // 67 MB fp32 per-slot GEMM2 output
__device__ __half   g_xh [(size_t)T_TOK * DM];
__device__ __half   g_wih[(size_t)NE * DFF * DM];
__device__ __half   g_woh[(size_t)NE * DM * DFF];

// ---------------------------------------------------------------- helpers
__device__ __forceinline__ uint32_t smem_u32(const void* p) {
    uint32_t a;
    asm("{ .reg .u64 t; cvta.to.shared.u64 t, %1; cvt.u32.u64 %0, t; }" : "=r"(a) : "l"(p));
    return a;
}

__device__ __forceinline__ void ldsm_x4(uint32_t r[4], uint32_t addr) {
    asm volatile("ldmatrix.sync.aligned.m8n8.x4.shared.b16 {%0,%1,%2,%3}, [%4];"
        : "=r"(r[0]), "=r"(r[1]), "=r"(r[2]), "=r"(r[3]) : "r"(addr));
}

__device__ __forceinline__ void mma_fp16(float c[4], const uint32_t a[4], uint32_t b0, uint32_t b1) {
    asm volatile(
        "mma.sync.aligned.m16n8k16.row.col.f32.f16.f16.f32 "
        "{%0,%1,%2,%3}, {%4,%5,%6,%7}, {%8,%9}, {%0,%1,%2,%3};"
        : "+f"(c[0]), "+f"(c[1]), "+f"(c[2]), "+f"(c[3])
        : "r"(a[0]), "r"(a[1]), "r"(a[2]), "r"(a[3]), "r"(b0), "r"(b1));
}

__device__ __forceinline__ void cpa16(uint32_t dst, const void* src, bool p) {
    int sz = p ? 16 : 0;
    asm volatile("cp.async.cg.shared.global [%0], [%1], 16, %2;\n" :: "r"(dst), "l"(src), "r"(sz));
}

// ---------------------------------------------------------------- small kernels
// fused: routing (blocks 0..63) + fp16 conversion of x/wi/wo (remaining blocks)
static constexpr int ROUTE_BLKS = CDIV(SLOTS, 256);   // 64

__global__ void k_prep(const int* __restrict__ sel, const float* __restrict__ rw,
                       const float4* __restrict__ x,  __half2* __restrict__ xh,  int nx,
                       const float4* __restrict__ wi, __half2* __restrict__ wih,
                       const float4* __restrict__ wo, __half2* __restrict__ woh, int nw)
{
    int bid = blockIdx.x;
    if (bid < ROUTE_BLKS) {
        int s = bid * blockDim.x + threadIdx.x;
        if (s >= SLOTS) return;
        const int* v = sel + (size_t)s * NE;
        int e = 0;
        #pragma unroll
        for (int i = 1; i < NE; i++) if (v[i] != 0) e = i;
        int pos = atomicAdd(&g_cnt[e], 1);
        g_tok[e][pos] = s / TOPK;
        g_sp[s] = ((uint32_t)e << 28) | (uint32_t)pos;
        return;
    }
    int i = (bid - ROUTE_BLKS) * blockDim.x + threadIdx.x;
    const float4* src; __half2* dst; int j;
    if (i < nx)              { src = x;  dst = xh;  j = i; }
    else if (i < nx + nw)    { src = wi; dst = wih; j = i - nx; }
    else if (i < nx + 2*nw)  { src = wo; dst = woh; j = i - nx - nw; }
    else return;
    float4 v = src[j];
    dst[2 * j]     = __floats2half2_rn(v.x, v.y);
    dst[2 * j + 1] = __floats2half2_rn(v.z, v.w);
}

__global__ void k_sched() {
    int b = 0, t = 0;
    for (int e = 0; e < NE; e++) {
        g_base[e] = b; g_toff[e] = t;
        int c = g_cnt[e];
        g_cntc[e] = c;
        g_cnt[e] = 0;                 // self-clean for next graph replay
        b += c;
        t += (c + TM - 1) / TM;
    }
    g_toff[NE] = t;
}

__global__ void k_combine(const float* __restrict__ rw, float4* __restrict__ out) {
    int idx = blockIdx.x * blockDim.x + threadIdx.x;     // T * 256
    int t = idx >> 8, j = idx & 255;
    uint32_t sp0 = g_sp[2 * t], sp1 = g_sp[2 * t + 1];
    size_t s0 = (size_t)(g_base[sp0 >> 28] + (int)(sp0 & 0x0FFFFFFF));
    size_t s1 = (size_t)(g_base[sp1 >> 28] + (int)(sp1 & 0x0FFFFFFF));
    float w0 = rw[2 * t], w1 = rw[2 * t + 1];
    const float4* y = (const float4*)g_y;
    float4 a = y[s0 * 256 + j];
    float4 b = y[s1 * 256 + j];
    float4 o;
    o.x = w0 * a.x + w1 * b.x;
    o.y = w0 * a.y + w1 * b.y;
    o.z = w0 * a.z + w1 * b.z;
    o.w = w0 * a.w + w1 * b.w;
    out[idx] = o;
}

// ---------------------------------------------------------------- grouped fp16 GEMM (R12 config, 4 stages)
// FIRST:  h[slot,n] = fp16(relu( x[tok,:] . wi[e][n,:] ))   KD=DM,  Ntot=DFF
// !FIRST: y[slot,n] = h[slot,:] . wo[e][n,:]                KD=DFF, Ntot=DM
template <bool FIRST, int KD>
__global__ __launch_bounds__(THREADS, 3) void k_gemm(const __half* __restrict__ Xin,
                                                     const __half* __restrict__ Wm)
{
    extern __shared__ char smem[];
    constexpr int Ntot = FIRST ? DFF : DM;
    constexpr int NK   = KD / KC;
    constexpr int KI   = KC / 16;                  // 2 kk-groups per stage

    int bx = blockIdx.x;
    int total = g_toff[NE];
    if (bx >= total) return;

    int e = 0;
    #pragma unroll
    for (int i = 1; i < NE; i++) if (bx >= g_toff[i]) e = i;
    int m0 = (bx - g_toff[e]) * TM, cnt = g_cntc[e], base = g_base[e];
    int n0 = blockIdx.y * TN;

    int tid  = threadIdx.x;
    int lane = tid & 31, w = tid >> 5;
    int g = lane >> 2, t4 = lane & 3;

    uint32_t sb = smem_u32(smem);

    // ---- loaders. A: 2 thr/row, 32B each (2 x 16B). B: 4 thr/row, 16B each.
    int rA  = tid >> 1;
    int coA = (tid & 1) * 32;                       // byte offset in 64B row
    int rB  = tid >> 2;
    int coB = (tid & 3) * 16;
    int mrowA = m0 + rA;
    bool aok = mrowA < cnt;
    const __half* aSrc;
    if (FIRST) {
        int tok = aok ? g_tok[e][mrowA] : 0;
        aSrc = Xin + (size_t)tok * KD;
    } else {
        aSrc = g_h + (size_t)(base + (aok ? mrowA : 0)) * KD;
    }
    const __half* bSrc = Wm + ((size_t)e * Ntot + n0 + rB) * KD;

    uint32_t aDst = sb + rA * PADB + coA;
    uint32_t bDst = sb + A_STAGE_B + rB * PADB + coB;

    auto load_stage = [&](int s) {
        uint32_t st = (uint32_t)((s % STAGES) * STAGE_BYTES);
        const __half* ap = aSrc + s * KC + coA / 2;
        const __half* bp = bSrc + s * KC + coB / 2;
        cpa16(aDst + st,      ap,     aok);
        cpa16(aDst + st + 16, ap + 8, aok);
        cpa16(bDst + st,      bp,     true);
    };

    #pragma unroll
    for (int s = 0; s < STAGES - 1; s++) {
        load_stage(s);
        asm volatile("cp.async.commit_group;\n");
    }

    // ---- warp tile 32x32: warps (4 m) x (2 n)
    int wm0 = (w & 3) * 32, wn0 = (w >> 2) * 32;
    int lrow = lane & 15;
    int khiB = ((lane >> 4) << 4);                  // 0 or 16B: k-half select

    uint32_t aOff[2], bOff[2];
    #pragma unroll
    for (int ms = 0; ms < 2; ms++)
        aOff[ms] = sb + (uint32_t)((wm0 + ms * 16 + lrow) * PADB) + khiB;
    #pragma unroll
    for (int nb = 0; nb < 2; nb++)
        bOff[nb] = sb + (uint32_t)(A_STAGE_B + (wn0 + nb * 16 + lrow) * PADB) + khiB;

    float acc[2][4][4];
    #pragma unroll
    for (int i = 0; i < 2; i++)
        #pragma unroll
        for (int j = 0; j < 4; j++)
            #pragma unroll
            for (int q = 0; q < 4; q++) acc[i][j][q] = 0.f;

    for (int s = 0; s < NK; s++) {
        asm volatile("cp.async.wait_group %0;\n" :: "n"(STAGES - 2));
        __syncthreads();

        // issue next gmem->smem loads (buffer (s+3)%4 — readers done at stage s-1)
        if (s + STAGES - 1 < NK) load_stage(s + STAGES - 1);
        asm volatile("cp.async.commit_group;\n");

        uint32_t st = (uint32_t)((s % STAGES) * STAGE_BYTES);
        #pragma unroll
        for (int kki = 0; kki < KI; kki++) {
            uint32_t kb = (uint32_t)(kki * 32);     // 16 halfs = 32B
            uint32_t a[2][4];
            #pragma unroll
            for (int ms = 0; ms < 2; ms++) ldsm_x4(a[ms], aOff[ms] + st + kb);
            #pragma unroll
            for (int nb = 0; nb < 2; nb++) {
                uint32_t bq[4];
                ldsm_x4(bq, bOff[nb] + st + kb);
                #pragma unroll
                for (int ms = 0; ms < 2; ms++) {
                    mma_fp16(acc[ms][nb * 2],     a[ms], bq[0], bq[2]);
                    mma_fp16(acc[ms][nb * 2 + 1], a[ms], bq[1], bq[3]);
                }
            }
        }
    }

    // ---- epilogue (no atomics: per-slot scratch)
    #pragma unroll
    for (int ms = 0; ms < 2; ms++) {
        #pragma unroll
        for (int half = 0; half < 2; half++) {
            int lr   = wm0 + ms * 16 + half * 8 + g;
            int mrow = m0 + lr;
            if (mrow < cnt) {
                if (FIRST) {
                    __half* hp = g_h + (size_t)(base + mrow) * DFF + n0 + wn0;
                    #pragma unroll
                    for (int ns = 0; ns < 4; ns++) {
                        float v0 = fmaxf(acc[ms][ns][half * 2 + 0], 0.f);
                        float v1 = fmaxf(acc[ms][ns][half * 2 + 1], 0.f);
                        *reinterpret_cast<__half2*>(hp + ns * 8 + 2 * t4) = __floats2half2_rn(v0, v1);
                    }
                } else {
                    float* yp = g_y + (size_t)(base + mrow) * DM + n0 + wn0;
                    #pragma unroll
                    for (int ns = 0; ns < 4; ns++) {
                        float2 st2;
                        st2.x = acc[ms][ns][half * 2 + 0];
                        st2.y = acc[ms][ns][half * 2 + 1];
                        *reinterpret_cast<float2*>(yp + ns * 8 + 2 * t4) = st2;
                    }
                }
            }
        }
    }
}

// ---------------------------------------------------------------- launch
extern "C" void kernel_launch(void* const* d_in, const int* in_sizes, int n_in,
                              void* d_out, int out_size)
{
    const float* x   = (const float*)d_in[0];   // [T, DM]
    const int*   sel = (const int*)  d_in[1];   // [T, K, E] one-hot int32
    const float* rw  = (const float*)d_in[2];   // [T, K]
    const float* wi  = (const float*)d_in[3];   // [E, DFF, DM]
    const float* wo  = (const float*)d_in[4];   // [E, DM, DFF]
    float* out = (float*)d_out;                 // [T, DM]

    __half* xh;  cudaGetSymbolAddress((void**)&xh,  g_xh);
    __half* wih; cudaGetSymbolAddress((void**)&wih, g_wih);
    __half* woh; cudaGetSymbolAddress((void**)&woh, g_woh);

    cudaFuncSetAttribute(k_gemm<true,  DM >, cudaFuncAttributeMaxDynamicSharedMemorySize, SMEM_TOTAL);
    cudaFuncSetAttribute(k_gemm<false, DFF>, cudaFuncAttributeMaxDynamicSharedMemorySize, SMEM_TOTAL);

    int nx = T_TOK * DM / 4;
    int nw = NE * DFF * DM / 4;

    k_prep<<<ROUTE_BLKS + CDIV(nx + 2 * nw, 256), 256>>>(
        sel, rw,
        (const float4*)x,  (__half2*)xh,  nx,
        (const float4*)wi, (__half2*)wih,
        (const float4*)wo, (__half2*)woh, nw);                                        // 1
    k_sched<<<1, 1>>>();                                                              // 2
    k_gemm<true,  DM ><<<dim3(MAXT, DFF / TN), THREADS, SMEM_TOTAL>>>(xh, wih);       // 3
    k_gemm<false, DFF><<<dim3(MAXT, DM  / TN), THREADS, SMEM_TOTAL>>>(nullptr, woh);  // 4 (profiled)
    k_combine<<<CDIV(T_TOK * DM / 4, 256), 256>>>(rw, (float4*)out);                  // 5
}

// round 17
// speedup vs baseline: 1.5873x; 1.0023x over previous
#include <cuda_runtime.h>
#include <cuda_fp16.h>
#include <cstdint>

#define CDIV(a,b) (((a)+(b)-1)/(b))

static constexpr int T_TOK = 8192;
static constexpr int DM    = 1024;
static constexpr int DFF   = 4096;
static constexpr int NE    = 8;
static constexpr int TOPK  = 2;
static constexpr int SLOTS = T_TOK * TOPK;      // 16384 routed slots

static constexpr int TM      = 128;
static constexpr int TN      = 64;
static constexpr int KC      = 32;              // K halfs per stage (64B row)
static constexpr int STAGES  = 4;
static constexpr int PADB    = 80;              // bytes per smem row (64 + 16 pad)
static constexpr int THREADS = 256;             // 8 warps, warp tile 32x32
static constexpr int MAXT    = SLOTS/TM + NE;   // 136 worst-case M tiles

static constexpr int A_STAGE_B   = TM * PADB;            // 10240
static constexpr int STAGE_BYTES = (TM + TN) * PADB;     // 15360
static constexpr int SMEM_TOTAL  = STAGES * STAGE_BYTES; // 61440 (3 CTA/SM = 184 KB)

// ---- device scratch (__device__ globals = sanctioned scratch path) ----
__device__ int      g_cnt[NE];                  // zeroed by k_sched tail (replay-safe)
__device__ int      g_cntc[NE];
__device__ int      g_base[NE];
__device__ int      g_toff[NE + 1];
__device__ int      g_tok[NE][SLOTS];
__device__ uint32_t g_sp[SLOTS];                // per input slot: (e<<28)|pos
__device__ __half   g_h  [(size_t)SLOTS * DFF]; // 134 MB fp16 activations
__device__ float    g_y  [(size_t)SLOTS * DM];  // 67 MB fp32 per-slot GEMM2 output
__device__ __half   g_xh [(size_t)T_TOK * DM];
__device__ __half   g_wih[(size_t)NE * DFF * DM];
__device__ __half   g_woh[(size_t)NE * DM * DFF];

// ---------------------------------------------------------------- helpers
__device__ __forceinline__ uint32_t smem_u32(const void* p) {
    uint32_t a;
    asm("{ .reg .u64 t; cvta.to.shared.u64 t, %1; cvt.u32.u64 %0, t; }" : "=r"(a) : "l"(p));
    return a;
}

__device__ __forceinline__ void ldsm_x4(uint32_t r[4], uint32_t addr) {
    asm volatile("ldmatrix.sync.aligned.m8n8.x4.shared.b16 {%0,%1,%2,%3}, [%4];"
        : "=r"(r[0]), "=r"(r[1]), "=r"(r[2]), "=r"(r[3]) : "r"(addr));
}

__device__ __forceinline__ void mma_fp16(float c[4], const uint32_t a[4], uint32_t b0, uint32_t b1) {
    asm volatile(
        "mma.sync.aligned.m16n8k16.row.col.f32.f16.f16.f32 "
        "{%0,%1,%2,%3}, {%4,%5,%6,%7}, {%8,%9}, {%0,%1,%2,%3};"
        : "+f"(c[0]), "+f"(c[1]), "+f"(c[2]), "+f"(c[3])
        : "r"(a[0]), "r"(a[1]), "r"(a[2]), "r"(a[3]), "r"(b0), "r"(b1));
}

__device__ __forceinline__ void cpa16(uint32_t dst, const void* src, bool p) {
    int sz = p ? 16 : 0;
    asm volatile("cp.async.cg.shared.global [%0], [%1], 16, %2;\n" :: "r"(dst), "l"(src), "r"(sz));
}

// ---------------------------------------------------------------- small kernels
// fused: routing (blocks 0..63) + fp16 conversion of x/wi/wo (remaining blocks)
static constexpr int ROUTE_BLKS = CDIV(SLOTS, 256);   // 64

__global__ void k_prep(const int* __restrict__ sel, const float* __restrict__ rw,
                       const float4* __restrict__ x,  __half2* __restrict__ xh,  int nx,
                       const float4* __restrict__ wi, __half2* __restrict__ wih,
                       const float4* __restrict__ wo, __half2* __restrict__ woh, int nw)
{
    int bid = blockIdx.x;
    if (bid < ROUTE_BLKS) {
        int s = bid * blockDim.x + threadIdx.x;
        if (s >= SLOTS) return;
        const int* v = sel + (size_t)s * NE;
        int e = 0;
        #pragma unroll
        for (int i = 1; i < NE; i++) if (v[i] != 0) e = i;
        int pos = atomicAdd(&g_cnt[e], 1);
        g_tok[e][pos] = s / TOPK;
        g_sp[s] = ((uint32_t)e << 28) | (uint32_t)pos;
        return;
    }
    int i = (bid - ROUTE_BLKS) * blockDim.x + threadIdx.x;
    const float4* src; __half2* dst; int j;
    if (i < nx)              { src = x;  dst = xh;  j = i; }
    else if (i < nx + nw)    { src = wi; dst = wih; j = i - nx; }
    else if (i < nx + 2*nw)  { src = wo; dst = woh; j = i - nx - nw; }
    else return;
    float4 v = src[j];
    dst[2 * j]     = __floats2half2_rn(v.x, v.y);
    dst[2 * j + 1] = __floats2half2_rn(v.z, v.w);
}

__global__ void k_sched() {
    int b = 0, t = 0;
    for (int e = 0; e < NE; e++) {
        g_base[e] = b; g_toff[e] = t;
        int c = g_cnt[e];
        g_cntc[e] = c;
        g_cnt[e] = 0;                 // self-clean for next graph replay
        b += c;
        t += (c + TM - 1) / TM;
    }
    g_toff[NE] = t;
}

__global__ void k_combine(const float* __restrict__ rw, float4* __restrict__ out) {
    int idx = blockIdx.x * blockDim.x + threadIdx.x;     // T * 256
    int t = idx >> 8, j = idx & 255;
    uint32_t sp0 = g_sp[2 * t], sp1 = g_sp[2 * t + 1];
    size_t s0 = (size_t)(g_base[sp0 >> 28] + (int)(sp0 & 0x0FFFFFFF));
    size_t s1 = (size_t)(g_base[sp1 >> 28] + (int)(sp1 & 0x0FFFFFFF));
    float w0 = rw[2 * t], w1 = rw[2 * t + 1];
    const float4* y = (const float4*)g_y;
    float4 a = y[s0 * 256 + j];
    float4 b = y[s1 * 256 + j];
    float4 o;
    o.x = w0 * a.x + w1 * b.x;
    o.y = w0 * a.y + w1 * b.y;
    o.z = w0 * a.z + w1 * b.z;
    o.w = w0 * a.w + w1 * b.w;
    out[idx] = o;
}

// ---------------------------------------------------------------- grouped fp16 GEMM
// FIRST:  h[slot,n] = fp16(relu( x[tok,:] . wi[e][n,:] ))   KD=DM,  Ntot=DFF
// !FIRST: y[slot,n] = h[slot,:] . wo[e][n,:]                KD=DFF, Ntot=DM
// SWAP: m-tile on blockIdx.y, n-tile on blockIdx.x (L2 locality for streamed A)
template <bool FIRST, int KD, bool SWAP>
__global__ __launch_bounds__(THREADS, 3) void k_gemm(const __half* __restrict__ Xin,
                                                     const __half* __restrict__ Wm)
{
    extern __shared__ char smem[];
    constexpr int Ntot = FIRST ? DFF : DM;
    constexpr int NK   = KD / KC;
    constexpr int KI   = KC / 16;                  // 2 kk-groups per stage

    int bx = SWAP ? blockIdx.y : blockIdx.x;       // m-tile index
    int by = SWAP ? blockIdx.x : blockIdx.y;       // n-tile index
    int total = g_toff[NE];
    if (bx >= total) return;

    int e = 0;
    #pragma unroll
    for (int i = 1; i < NE; i++) if (bx >= g_toff[i]) e = i;
    int m0 = (bx - g_toff[e]) * TM, cnt = g_cntc[e], base = g_base[e];
    int n0 = by * TN;

    int tid  = threadIdx.x;
    int lane = tid & 31, w = tid >> 5;
    int g = lane >> 2, t4 = lane & 3;

    uint32_t sb = smem_u32(smem);

    // ---- loaders. A: 2 thr/row, 32B each (2 x 16B). B: 4 thr/row, 16B each.
    int rA  = tid >> 1;
    int coA = (tid & 1) * 32;                       // byte offset in 64B row
    int rB  = tid >> 2;
    int coB = (tid & 3) * 16;
    int mrowA = m0 + rA;
    bool aok = mrowA < cnt;
    const __half* aSrc;
    if (FIRST) {
        int tok = aok ? g_tok[e][mrowA] : 0;
        aSrc = Xin + (size_t)tok * KD;
    } else {
        aSrc = g_h + (size_t)(base + (aok ? mrowA : 0)) * KD;
    }
    const __half* bSrc = Wm + ((size_t)e * Ntot + n0 + rB) * KD;

    uint32_t aDst = sb + rA * PADB + coA;
    uint32_t bDst = sb + A_STAGE_B + rB * PADB + coB;

    auto load_stage = [&](int s) {
        uint32_t st = (uint32_t)((s % STAGES) * STAGE_BYTES);
        const __half* ap = aSrc + s * KC + coA / 2;
        const __half* bp = bSrc + s * KC + coB / 2;
        cpa16(aDst + st,      ap,     aok);
        cpa16(aDst + st + 16, ap + 8, aok);
        cpa16(bDst + st,      bp,     true);
    };

    #pragma unroll
    for (int s = 0; s < STAGES - 1; s++) {
        load_stage(s);
        asm volatile("cp.async.commit_group;\n");
    }

    // ---- warp tile 32x32: warps (4 m) x (2 n)
    int wm0 = (w & 3) * 32, wn0 = (w >> 2) * 32;
    int lrow = lane & 15;
    int khiB = ((lane >> 4) << 4);                  // 0 or 16B: k-half select

    uint32_t aOff[2], bOff[2];
    #pragma unroll
    for (int ms = 0; ms < 2; ms++)
        aOff[ms] = sb + (uint32_t)((wm0 + ms * 16 + lrow) * PADB) + khiB;
    #pragma unroll
    for (int nb = 0; nb < 2; nb++)
        bOff[nb] = sb + (uint32_t)(A_STAGE_B + (wn0 + nb * 16 + lrow) * PADB) + khiB;

    float acc[2][4][4];
    #pragma unroll
    for (int i = 0; i < 2; i++)
        #pragma unroll
        for (int j = 0; j < 4; j++)
            #pragma unroll
            for (int q = 0; q < 4; q++) acc[i][j][q] = 0.f;

    for (int s = 0; s < NK; s++) {
        asm volatile("cp.async.wait_group %0;\n" :: "n"(STAGES - 2));
        __syncthreads();

        // issue next gmem->smem loads (buffer (s+3)%4 — readers done at stage s-1)
        if (s + STAGES - 1 < NK) load_stage(s + STAGES - 1);
        asm volatile("cp.async.commit_group;\n");

        uint32_t st = (uint32_t)((s % STAGES) * STAGE_BYTES);
        #pragma unroll
        for (int kki = 0; kki < KI; kki++) {
            uint32_t kb = (uint32_t)(kki * 32);     // 16 halfs = 32B
            uint32_t a[2][4];
            #pragma unroll
            for (int ms = 0; ms < 2; ms++) ldsm_x4(a[ms], aOff[ms] + st + kb);
            #pragma unroll
            for (int nb = 0; nb < 2; nb++) {
                uint32_t bq[4];
                ldsm_x4(bq, bOff[nb] + st + kb);
                #pragma unroll
                for (int ms = 0; ms < 2; ms++) {
                    mma_fp16(acc[ms][nb * 2],     a[ms], bq[0], bq[2]);
                    mma_fp16(acc[ms][nb * 2 + 1], a[ms], bq[1], bq[3]);
                }
            }
        }
    }

    // ---- epilogue (no atomics: per-slot scratch)
    #pragma unroll
    for (int ms = 0; ms < 2; ms++) {
        #pragma unroll
        for (int half = 0; half < 2; half++) {
            int lr   = wm0 + ms * 16 + half * 8 + g;
            int mrow = m0 + lr;
            if (mrow < cnt) {
                if (FIRST) {
                    __half* hp = g_h + (size_t)(base + mrow) * DFF + n0 + wn0;
                    #pragma unroll
                    for (int ns = 0; ns < 4; ns++) {
                        float v0 = fmaxf(acc[ms][ns][half * 2 + 0], 0.f);
                        float v1 = fmaxf(acc[ms][ns][half * 2 + 1], 0.f);
                        *reinterpret_cast<__half2*>(hp + ns * 8 + 2 * t4) = __floats2half2_rn(v0, v1);
                    }
                } else {
                    float* yp = g_y + (size_t)(base + mrow) * DM + n0 + wn0;
                    #pragma unroll
                    for (int ns = 0; ns < 4; ns++) {
                        float2 st2;
                        st2.x = acc[ms][ns][half * 2 + 0];
                        st2.y = acc[ms][ns][half * 2 + 1];
                        *reinterpret_cast<float2*>(yp + ns * 8 + 2 * t4) = st2;
                    }
                }
            }
        }
    }
}

// ---------------------------------------------------------------- launch
extern "C" void kernel_launch(void* const* d_in, const int* in_sizes, int n_in,
                              void* d_out, int out_size)
{
    const float* x   = (const float*)d_in[0];   // [T, DM]
    const int*   sel = (const int*)  d_in[1];   // [T, K, E] one-hot int32
    const float* rw  = (const float*)d_in[2];   // [T, K]
    const float* wi  = (const float*)d_in[3];   // [E, DFF, DM]
    const float* wo  = (const float*)d_in[4];   // [E, DM, DFF]
    float* out = (float*)d_out;                 // [T, DM]

    __half* xh;  cudaGetSymbolAddress((void**)&xh,  g_xh);
    __half* wih; cudaGetSymbolAddress((void**)&wih, g_wih);
    __half* woh; cudaGetSymbolAddress((void**)&woh, g_woh);

    cudaFuncSetAttribute((const void*)k_gemm<true,  DM,  false>, cudaFuncAttributeMaxDynamicSharedMemorySize, SMEM_TOTAL);
    cudaFuncSetAttribute((const void*)k_gemm<false, DFF, true >, cudaFuncAttributeMaxDynamicSharedMemorySize, SMEM_TOTAL);

    int nx = T_TOK * DM / 4;
    int nw = NE * DFF * DM / 4;

    k_prep<<<ROUTE_BLKS + CDIV(nx + 2 * nw, 256), 256>>>(
        sel, rw,
        (const float4*)x,  (__half2*)xh,  nx,
        (const float4*)wi, (__half2*)wih,
        (const float4*)wo, (__half2*)woh, nw);                                        // 1
    k_sched<<<1, 1>>>();                                                              // 2
    k_gemm<true,  DM,  false><<<dim3(MAXT, DFF / TN), THREADS, SMEM_TOTAL>>>(xh, wih);  // 3
    k_gemm<false, DFF, true ><<<dim3(DM / TN, MAXT), THREADS, SMEM_TOTAL>>>(nullptr, woh); // 4 (profiled)
    k_combine<<<CDIV(T_TOK * DM / 4, 256), 256>>>(rw, (float4*)out);                  // 5
}